// round 1
// baseline (speedup 1.0000x reference)
#include <cuda_runtime.h>
#include <cuda_bf16.h>

#define N_NODES 50000
#define D 32

// Node-level scratch (device globals — no allocation allowed in kernel_launch).
__device__ float g_seg[N_NODES * D];   // step 1 accumulator -> node_mean (in place)
__device__ float g_deg[N_NODES];       // in-degree
__device__ float g_h[N_NODES * D];     // step 2 accumulator
__device__ float g_g[N_NODES * D];     // g = h @ W.T  (node-level linear, no bias)

// ---------------------------------------------------------------------------
// K1: zero accumulators
// ---------------------------------------------------------------------------
__global__ void k_zero() {
    int i = blockIdx.x * blockDim.x + threadIdx.x;
    if (i < N_NODES * D) {
        g_seg[i] = 0.0f;
        g_h[i]   = 0.0f;
    }
    if (i < N_NODES) g_deg[i] = 0.0f;
}

// ---------------------------------------------------------------------------
// K2: seg_sum[dst] += edge_feats[e]; deg[dst] += 1
// Thread per (edge, d). Consecutive threads -> consecutive d: coalesced reads.
// ---------------------------------------------------------------------------
__global__ void k_scatter_feats(const float* __restrict__ ef,
                                const int* __restrict__ dst, int E) {
    int t = blockIdx.x * blockDim.x + threadIdx.x;   // E*D = 51.2M fits in int
    if (t >= E * D) return;
    int e = t >> 5;
    int d = t & 31;
    float v = ef[t];
    int n = dst[e];                                   // broadcast within 32-thread group
    atomicAdd(&g_seg[n * D + d], v);
    if (d == 0) atomicAdd(&g_deg[n], 1.0f);
}

// ---------------------------------------------------------------------------
// K3: node_mean = seg_sum / max(deg, 1)   (in place)
// ---------------------------------------------------------------------------
__global__ void k_normalize() {
    int i = blockIdx.x * blockDim.x + threadIdx.x;
    if (i >= N_NODES * D) return;
    float dg = g_deg[i >> 5];
    g_seg[i] = g_seg[i] / fmaxf(dg, 1.0f);
}

// ---------------------------------------------------------------------------
// K4: h[dst] += node_mean[src]   (gather row, scatter-add row)
// ---------------------------------------------------------------------------
__global__ void k_gather_scatter(const int* __restrict__ src,
                                 const int* __restrict__ dst, int E) {
    int t = blockIdx.x * blockDim.x + threadIdx.x;
    if (t >= E * D) return;
    int e = t >> 5;
    int d = t & 31;
    int ns = src[e];
    int nd = dst[e];
    float v = g_seg[ns * D + d];                      // 128B coalesced row, L2-resident
    atomicAdd(&g_h[nd * D + d], v);
}

// ---------------------------------------------------------------------------
// K5: g = h @ W.T   (per node; 50K x 32x32). Thread per (node, j).
// W in shared with +1 pad to kill the 32-way bank conflict (j*32+i -> j*33+i).
// ---------------------------------------------------------------------------
__global__ void k_node_gemm(const float* __restrict__ W) {
    __shared__ float Ws[D * (D + 1)];
    for (int i = threadIdx.x; i < D * D; i += blockDim.x) {
        int r = i / D, c = i % D;
        Ws[r * (D + 1) + c] = W[i];
    }
    __syncthreads();
    int t = blockIdx.x * blockDim.x + threadIdx.x;
    if (t >= N_NODES * D) return;
    int n = t >> 5;
    int j = t & 31;
    const float* hr = &g_h[n * D];
    float acc = 0.0f;
#pragma unroll
    for (int i = 0; i < D; i++)
        acc = fmaf(hr[i], Ws[j * (D + 1) + i], acc);  // hr[i] broadcast across warp
    g_g[t] = acc;
}

// ---------------------------------------------------------------------------
// K6: out[e] = 0.5*(g[src[e]] + g[dst[e]]) + b
// g is 6.4MB -> L2-resident gathers; out write is coalesced.
// ---------------------------------------------------------------------------
__global__ void k_edge_out(const int* __restrict__ src,
                           const int* __restrict__ dst,
                           const float* __restrict__ b,
                           float* __restrict__ out, int E) {
    __shared__ float bs[D];
    if (threadIdx.x < D) bs[threadIdx.x] = b[threadIdx.x];
    __syncthreads();
    int t = blockIdx.x * blockDim.x + threadIdx.x;
    if (t >= E * D) return;
    int e = t >> 5;
    int d = t & 31;
    int ns = src[e];
    int nd = dst[e];
    out[t] = 0.5f * (g_g[ns * D + d] + g_g[nd * D + d]) + bs[d];
}

// ---------------------------------------------------------------------------
// Launch
// ---------------------------------------------------------------------------
extern "C" void kernel_launch(void* const* d_in, const int* in_sizes, int n_in,
                              void* d_out, int out_size) {
    const float* edge_feats = (const float*)d_in[0];
    const int*   src        = (const int*)d_in[1];
    const int*   dst        = (const int*)d_in[2];
    const float* W          = (const float*)d_in[3];
    const float* b          = (const float*)d_in[4];
    float*       out        = (float*)d_out;

    const int E = in_sizes[1];            // number of edges (src element count)
    const int TPB = 256;

    const int node_elems = N_NODES * D;
    const int edge_elems = E * D;

    k_zero<<<(node_elems + TPB - 1) / TPB, TPB>>>();
    k_scatter_feats<<<(edge_elems + TPB - 1) / TPB, TPB>>>(edge_feats, dst, E);
    k_normalize<<<(node_elems + TPB - 1) / TPB, TPB>>>();
    k_gather_scatter<<<(edge_elems + TPB - 1) / TPB, TPB>>>(src, dst, E);
    k_node_gemm<<<(node_elems + TPB - 1) / TPB, TPB>>>(W);
    k_edge_out<<<(edge_elems + TPB - 1) / TPB, TPB>>>(src, dst, b, out, E);
}

// round 2
// speedup vs baseline: 2.6035x; 2.6035x over previous
#include <cuda_runtime.h>
#include <cuda_bf16.h>

#define N_NODES 50000
#define D 32
#define D4 8            // floats4 per row

// Node-level scratch (device globals — no allocation allowed in kernel_launch).
__device__ float g_seg[N_NODES * D];   // step 1 accumulator -> node_mean (in place)
__device__ float g_deg[N_NODES];       // in-degree
__device__ float g_h[N_NODES * D];     // step 2 accumulator
__device__ float g_g[N_NODES * D];     // g = h @ W.T  (node-level linear, no bias)

__device__ __forceinline__ void red_add_v4(float* ptr, float4 v) {
    asm volatile("red.global.add.v4.f32 [%0], {%1, %2, %3, %4};"
                 :: "l"(ptr), "f"(v.x), "f"(v.y), "f"(v.z), "f"(v.w)
                 : "memory");
}

// ---------------------------------------------------------------------------
// K1: zero accumulators (vectorized)
// ---------------------------------------------------------------------------
__global__ void k_zero() {
    int i = blockIdx.x * blockDim.x + threadIdx.x;   // over N_NODES * D4
    if (i < N_NODES * D4) {
        ((float4*)g_seg)[i] = make_float4(0.f, 0.f, 0.f, 0.f);
        ((float4*)g_h)[i]   = make_float4(0.f, 0.f, 0.f, 0.f);
    }
    if (i < N_NODES) g_deg[i] = 0.0f;
}

// ---------------------------------------------------------------------------
// K2: seg_sum[dst] += edge_feats[e]; deg[dst] += 1
// Thread per (edge, d4). 8 threads per edge, float4 each.
// ---------------------------------------------------------------------------
__global__ void k_scatter_feats(const float4* __restrict__ ef,
                                const int* __restrict__ dst, int E) {
    int t = blockIdx.x * blockDim.x + threadIdx.x;   // over E * D4 = 12.8M
    if (t >= E * D4) return;
    int e  = t >> 3;
    int d4 = t & 7;
    float4 v = ef[t];
    int n = dst[e];
    red_add_v4(&g_seg[n * D + d4 * 4], v);
    if (d4 == 0) atomicAdd(&g_deg[n], 1.0f);
}

// ---------------------------------------------------------------------------
// K3: node_mean = seg_sum / max(deg, 1)   (in place, vectorized)
// ---------------------------------------------------------------------------
__global__ void k_normalize() {
    int i = blockIdx.x * blockDim.x + threadIdx.x;   // over N_NODES * D4
    if (i >= N_NODES * D4) return;
    float inv = 1.0f / fmaxf(g_deg[i >> 3], 1.0f);
    float4 v = ((float4*)g_seg)[i];
    v.x *= inv; v.y *= inv; v.z *= inv; v.w *= inv;
    ((float4*)g_seg)[i] = v;
}

// ---------------------------------------------------------------------------
// K4: h[dst] += node_mean[src]   (gather float4, vector-red float4)
// ---------------------------------------------------------------------------
__global__ void k_gather_scatter(const int* __restrict__ src,
                                 const int* __restrict__ dst, int E) {
    int t = blockIdx.x * blockDim.x + threadIdx.x;   // over E * D4
    if (t >= E * D4) return;
    int e  = t >> 3;
    int d4 = t & 7;
    int ns = src[e];
    int nd = dst[e];
    float4 v = *(const float4*)&g_seg[ns * D + d4 * 4];  // L2-resident
    red_add_v4(&g_h[nd * D + d4 * 4], v);
}

// ---------------------------------------------------------------------------
// K5: g = h @ W.T   (per node; 50K x 32x32). Thread per (node, j).
// W in shared with +1 pad to kill bank conflicts.
// ---------------------------------------------------------------------------
__global__ void k_node_gemm(const float* __restrict__ W) {
    __shared__ float Ws[D * (D + 1)];
    for (int i = threadIdx.x; i < D * D; i += blockDim.x) {
        int r = i / D, c = i % D;
        Ws[r * (D + 1) + c] = W[i];
    }
    __syncthreads();
    int t = blockIdx.x * blockDim.x + threadIdx.x;
    if (t >= N_NODES * D) return;
    int n = t >> 5;
    int j = t & 31;
    const float* hr = &g_h[n * D];
    float acc = 0.0f;
#pragma unroll
    for (int i = 0; i < D; i++)
        acc = fmaf(hr[i], Ws[j * (D + 1) + i], acc);  // hr[i] broadcast across warp
    g_g[t] = acc;
}

// ---------------------------------------------------------------------------
// K6: out[e] = 0.5*(g[src[e]] + g[dst[e]]) + b   (float4 everywhere)
// ---------------------------------------------------------------------------
__global__ void k_edge_out(const int* __restrict__ src,
                           const int* __restrict__ dst,
                           const float* __restrict__ b,
                           float4* __restrict__ out, int E) {
    __shared__ float4 bs[D4];
    if (threadIdx.x < D4) {
        bs[threadIdx.x] = *(const float4*)&b[threadIdx.x * 4];
    }
    __syncthreads();
    int t = blockIdx.x * blockDim.x + threadIdx.x;   // over E * D4
    if (t >= E * D4) return;
    int e  = t >> 3;
    int d4 = t & 7;
    int ns = src[e];
    int nd = dst[e];
    float4 a = *(const float4*)&g_g[ns * D + d4 * 4];
    float4 c = *(const float4*)&g_g[nd * D + d4 * 4];
    float4 bb = bs[d4];
    float4 o;
    o.x = fmaf(0.5f, a.x + c.x, bb.x);
    o.y = fmaf(0.5f, a.y + c.y, bb.y);
    o.z = fmaf(0.5f, a.z + c.z, bb.z);
    o.w = fmaf(0.5f, a.w + c.w, bb.w);
    out[t] = o;
}

// ---------------------------------------------------------------------------
// Launch
// ---------------------------------------------------------------------------
extern "C" void kernel_launch(void* const* d_in, const int* in_sizes, int n_in,
                              void* d_out, int out_size) {
    const float* edge_feats = (const float*)d_in[0];
    const int*   src        = (const int*)d_in[1];
    const int*   dst        = (const int*)d_in[2];
    const float* W          = (const float*)d_in[3];
    const float* b          = (const float*)d_in[4];

    const int E = in_sizes[1];            // number of edges
    const int TPB = 256;

    const int node_v4  = N_NODES * D4;    // 400K
    const int node_el  = N_NODES * D;     // 1.6M
    const int edge_v4  = E * D4;          // 12.8M

    k_zero<<<(node_v4 + TPB - 1) / TPB, TPB>>>();
    k_scatter_feats<<<(edge_v4 + TPB - 1) / TPB, TPB>>>(
        (const float4*)edge_feats, dst, E);
    k_normalize<<<(node_v4 + TPB - 1) / TPB, TPB>>>();
    k_gather_scatter<<<(edge_v4 + TPB - 1) / TPB, TPB>>>(src, dst, E);
    k_node_gemm<<<(node_el + TPB - 1) / TPB, TPB>>>(W);
    k_edge_out<<<(edge_v4 + TPB - 1) / TPB, TPB>>>(src, dst, b, (float4*)d_out, E);
}